// round 9
// baseline (speedup 1.0000x reference)
#include <cuda_runtime.h>
#include <cstdint>
#include <math_constants.h>

#define TOKENS   32768
#define DIM      2048
#define NE       64
#define TOPK     6

#define BM       128              // tokens per CTA
#define BKT      32               // K per chunk
#define NCHUNK   (DIM / BKT)      // 64
#define THREADS  256              // 8 warps: 4 across M (32 rows), 2 across N (32 cols)

#define KB2      40               // bf16 row stride (elements): 32 + 8 pad -> conflict-free frags
#define ROWB     (KB2 * 2)        // 80 bytes per row

#define OFF_AH   0
#define OFF_AM   (BM * ROWB)          // 10240
#define OFF_AL   (2 * BM * ROWB)      // 20480
#define OFF_WH   (3 * BM * ROWB)      // 30720
#define OFF_WM   (3 * BM * ROWB + NE * ROWB)       // 35840
#define OFF_WL   (3 * BM * ROWB + 2 * NE * ROWB)   // 40960
#define STAGE_B  (3 * BM * ROWB + 3 * NE * ROWB)   // 46080
#define BIAS_OFF (2 * STAGE_B)
#define CNT_OFF  (BIAS_OFF + 256)
#define SMEM_BYTES (CNT_OFF + 16)

#define LSTR     66               // epilogue logits row stride (floats)
#define FLAG_GAP 1e-5f

// ---- flagged-token lists, per gate block (overwritten every replay) ----
__device__ int g_cnt[256];
__device__ int g_flags[256 * BM];

// pack two fp32 -> bf16x2 (hi elem = a, lo elem = b), round-to-nearest
__device__ __forceinline__ uint32_t pack_bf16(float hi, float lo) {
    uint32_t d;
    asm("cvt.rn.bf16x2.f32 %0, %1, %2;" : "=r"(d) : "f"(hi), "f"(lo));
    return d;
}
__device__ __forceinline__ float bf_lo(uint32_t p) { return __uint_as_float(p << 16); }
__device__ __forceinline__ float bf_hi(uint32_t p) { return __uint_as_float(p & 0xFFFF0000u); }

struct Tri { uint2 h, m, l; };
// exact-ish 3-way bf16 split of 4 consecutive values (residual ~2^-25)
__device__ __forceinline__ Tri split4(float4 v) {
    Tri t;
    t.h.x = pack_bf16(v.y, v.x);
    t.h.y = pack_bf16(v.w, v.z);
    float r0 = v.x - bf_lo(t.h.x), r1 = v.y - bf_hi(t.h.x);
    float r2 = v.z - bf_lo(t.h.y), r3 = v.w - bf_hi(t.h.y);
    t.m.x = pack_bf16(r1, r0);
    t.m.y = pack_bf16(r3, r2);
    float s0 = r0 - bf_lo(t.m.x), s1 = r1 - bf_hi(t.m.x);
    float s2 = r2 - bf_lo(t.m.y), s3 = r3 - bf_hi(t.m.y);
    t.l.x = pack_bf16(s1, s0);
    t.l.y = pack_bf16(s3, s2);
    return t;
}

// m16n8k16 bf16 mma, f32 accumulate in-place
__device__ __forceinline__ void mma16(float* c, const uint32_t* a, uint32_t b0, uint32_t b1) {
    asm volatile(
        "mma.sync.aligned.m16n8k16.row.col.f32.bf16.bf16.f32 "
        "{%0,%1,%2,%3}, {%4,%5,%6,%7}, {%8,%9}, {%0,%1,%2,%3};"
        : "+f"(c[0]), "+f"(c[1]), "+f"(c[2]), "+f"(c[3])
        : "r"(a[0]), "r"(a[1]), "r"(a[2]), "r"(a[3]), "r"(b0), "r"(b1));
}

// ============================ PASS 1: bf16 6-term MMA GEMM + gate ============================
__global__ __launch_bounds__(THREADS, 2)
void gate_kernel(const float* __restrict__ x,
                 const float* __restrict__ w,
                 const float* __restrict__ bias,
                 float* __restrict__ out)
{
    extern __shared__ __align__(16) unsigned char smem[];
    float* sBias = reinterpret_cast<float*>(smem + BIAS_OFF);
    int*   sCnt  = reinterpret_cast<int*>(smem + CNT_OFF);
    float* sLog  = reinterpret_cast<float*>(smem);   // epilogue overlay

    const int tid  = threadIdx.x;
    const int lane = tid & 31;
    const int wid  = tid >> 5;
    const int gid  = lane >> 2;      // 0..7
    const int tg   = lane & 3;       // 0..3
    const int m0   = (wid & 3) * 32;
    const int n0   = (wid >> 2) * 32;
    const int block_m = blockIdx.x * BM;

    if (tid < NE) sBias[tid] = bias[tid];
    if (tid == 0) sCnt[0] = 0;

    const float* xg = x + (size_t)block_m * DIM;

    float acc[2][4][4];
    #pragma unroll
    for (int mt = 0; mt < 2; mt++)
        #pragma unroll
        for (int nt = 0; nt < 4; nt++)
            #pragma unroll
            for (int r = 0; r < 4; r++) acc[mt][nt][r] = 0.f;

    // LDG tiling: x 4 float4/thread, w 2 float4/thread per chunk
    float4 xr[4], wr[2];
    int xtok[4], xcq[4], wexp[2], wcq[2];
    #pragma unroll
    for (int i = 0; i < 4; i++) {
        int li = i * THREADS + tid; xtok[i] = li >> 3; xcq[i] = li & 7;
    }
    #pragma unroll
    for (int i = 0; i < 2; i++) {
        int li = i * THREADS + tid; wexp[i] = li >> 3; wcq[i] = li & 7;
    }

    auto ldg_chunk = [&](int c) {
        int k0 = c * BKT;
        #pragma unroll
        for (int i = 0; i < 4; i++)
            xr[i] = *reinterpret_cast<const float4*>(xg + (size_t)xtok[i] * DIM + k0 + xcq[i] * 4);
        #pragma unroll
        for (int i = 0; i < 2; i++)
            wr[i] = *reinterpret_cast<const float4*>(w + (size_t)wexp[i] * DIM + k0 + wcq[i] * 4);
    };
    // split regs -> three bf16 comp arrays in stage s
    auto sts_chunk = [&](int s) {
        unsigned char* st = smem + s * STAGE_B;
        #pragma unroll
        for (int i = 0; i < 4; i++) {
            Tri t = split4(xr[i]);
            int off = xtok[i] * ROWB + xcq[i] * 8;
            *reinterpret_cast<uint2*>(st + OFF_AH + off) = t.h;
            *reinterpret_cast<uint2*>(st + OFF_AM + off) = t.m;
            *reinterpret_cast<uint2*>(st + OFF_AL + off) = t.l;
        }
        #pragma unroll
        for (int i = 0; i < 2; i++) {
            Tri t = split4(wr[i]);
            int off = wexp[i] * ROWB + wcq[i] * 8;
            *reinterpret_cast<uint2*>(st + OFF_WH + off) = t.h;
            *reinterpret_cast<uint2*>(st + OFF_WM + off) = t.m;
            *reinterpret_cast<uint2*>(st + OFF_WL + off) = t.l;
        }
    };

    ldg_chunk(0);
    sts_chunk(0);
    __syncthreads();
    ldg_chunk(1);

    for (int c = 0; c < NCHUNK; c++) {
        const int s = c & 1;
        if (c + 1 < NCHUNK) {
            sts_chunk(s ^ 1);
            if (c + 2 < NCHUNK) ldg_chunk(c + 2);
        }

        const unsigned char* st = smem + s * STAGE_B;
        const uint32_t* Ah = reinterpret_cast<const uint32_t*>(st + OFF_AH);
        const uint32_t* Am = reinterpret_cast<const uint32_t*>(st + OFF_AM);
        const uint32_t* Al = reinterpret_cast<const uint32_t*>(st + OFF_AL);
        const uint32_t* Wh = reinterpret_cast<const uint32_t*>(st + OFF_WH);
        const uint32_t* Wm = reinterpret_cast<const uint32_t*>(st + OFF_WM);
        const uint32_t* Wl = reinterpret_cast<const uint32_t*>(st + OFF_WL);

        #pragma unroll
        for (int q = 0; q < BKT / 16; q++) {
            const int kw = q * 8 + tg;      // word offset of k-pair (k = 2*word)

            // ---- A fragments: 2 m-tiles x 3 components ----
            uint32_t ah[2][4], am[2][4], al[2][4];
            #pragma unroll
            for (int mt = 0; mt < 2; mt++) {
                int r0 = (m0 + mt * 16 + gid) * (ROWB / 4);
                int r1 = r0 + 8 * (ROWB / 4);
                ah[mt][0] = Ah[r0 + kw];     ah[mt][1] = Ah[r1 + kw];
                ah[mt][2] = Ah[r0 + kw + 4]; ah[mt][3] = Ah[r1 + kw + 4];
                am[mt][0] = Am[r0 + kw];     am[mt][1] = Am[r1 + kw];
                am[mt][2] = Am[r0 + kw + 4]; am[mt][3] = Am[r1 + kw + 4];
                al[mt][0] = Al[r0 + kw];     al[mt][1] = Al[r1 + kw];
                al[mt][2] = Al[r0 + kw + 4]; al[mt][3] = Al[r1 + kw + 4];
            }

            #pragma unroll
            for (int nt = 0; nt < 4; nt++) {
                int rn = (n0 + nt * 8 + gid) * (ROWB / 4);
                uint32_t bh0 = Wh[rn + kw], bh1 = Wh[rn + kw + 4];
                uint32_t bm0 = Wm[rn + kw], bm1 = Wm[rn + kw + 4];
                uint32_t bl0 = Wl[rn + kw], bl1 = Wl[rn + kw + 4];
                #pragma unroll
                for (int mt = 0; mt < 2; mt++) {
                    float* cc = acc[mt][nt];
                    mma16(cc, ah[mt], bh0, bh1);   // hi*hi
                    mma16(cc, ah[mt], bm0, bm1);   // hi*mid
                    mma16(cc, am[mt], bh0, bh1);   // mid*hi
                    mma16(cc, am[mt], bm0, bm1);   // mid*mid
                    mma16(cc, ah[mt], bl0, bl1);   // hi*lo
                    mma16(cc, al[mt], bh0, bh1);   // lo*hi
                }
            }
        }
        __syncthreads();
    }

    // ---- dump logits ----
    #pragma unroll
    for (int mt = 0; mt < 2; mt++)
        #pragma unroll
        for (int nt = 0; nt < 4; nt++) {
            int row = m0 + mt * 16 + gid;
            int col = n0 + nt * 8 + tg * 2;
            *reinterpret_cast<float2*>(&sLog[row * LSTR + col]) =
                make_float2(acc[mt][nt][0], acc[mt][nt][1]);
            *reinterpret_cast<float2*>(&sLog[(row + 8) * LSTR + col]) =
                make_float2(acc[mt][nt][2], acc[mt][nt][3]);
        }
    __syncthreads();

    // ---- epilogue: softmax, top-6, ambiguity flag ----
    if (tid < BM) {
        float* row = sLog + tid * LSTR;

        float m = row[0];
        #pragma unroll
        for (int e = 1; e < NE; e++) m = fmaxf(m, row[e]);
        float ssum = 0.f;
        #pragma unroll
        for (int e = 0; e < NE; e++) { float ex = __expf(row[e] - m); row[e] = ex; ssum += ex; }
        float inv = 1.0f / ssum;
        #pragma unroll
        for (int e = 0; e < NE; e++) row[e] *= inv;

        const int t = block_m + tid;
        float* outw = out + (size_t)t * TOPK;
        float* outi = out + (size_t)TOKENS * TOPK + (size_t)t * TOPK;

        float prev = 0.f, minGap = CUDART_INF_F;
        #pragma unroll
        for (int k = 0; k < TOPK + 1; k++) {
            float best = -CUDART_INF_F; int bi = 0;
            #pragma unroll
            for (int e = 0; e < NE; e++) {
                float b = row[e] + sBias[e];
                if (b > best) { best = b; bi = e; }
            }
            if (k > 0) minGap = fminf(minGap, prev - best);
            prev = best;
            if (k < TOPK) {
                outw[k] = row[bi];
                outi[k] = (float)bi;
                row[bi] = -CUDART_INF_F;
            }
        }
        if (minGap < FLAG_GAP) {
            int idx = atomicAdd(sCnt, 1);
            g_flags[blockIdx.x * BM + idx] = t;
        }
    }
    __syncthreads();
    if (tid == 0) g_cnt[blockIdx.x] = sCnt[0];
}

// ============ PASS 2: fp32-exact scalar recompute for flagged tokens ============
__global__ __launch_bounds__(64)
void fix_kernel(const float* __restrict__ x,
                const float* __restrict__ w,
                const float* __restrict__ bias,
                float* __restrict__ out)
{
    __shared__ float srow[2][NE];
    const int cnt = g_cnt[blockIdx.x];
    if (cnt == 0) return;
    const int lane = threadIdx.x & 31;
    const int warp = threadIdx.x >> 5;

    for (int i = warp; i < cnt; i += 2) {
        const int tok = g_flags[blockIdx.x * BM + i];
        const float* xt = x + (size_t)tok * DIM;
        const float* w0 = w + (size_t)lane * DIM;
        const float* w1 = w + (size_t)(lane + 32) * DIM;

        float a0 = 0.f, a1 = 0.f;
        for (int k = 0; k < DIM; k += 4) {
            float4 xv  = *reinterpret_cast<const float4*>(xt + k);
            float4 wv0 = *reinterpret_cast<const float4*>(w0 + k);
            float4 wv1 = *reinterpret_cast<const float4*>(w1 + k);
            a0 = fmaf(xv.x, wv0.x, a0); a0 = fmaf(xv.y, wv0.y, a0);
            a0 = fmaf(xv.z, wv0.z, a0); a0 = fmaf(xv.w, wv0.w, a0);
            a1 = fmaf(xv.x, wv1.x, a1); a1 = fmaf(xv.y, wv1.y, a1);
            a1 = fmaf(xv.z, wv1.z, a1); a1 = fmaf(xv.w, wv1.w, a1);
        }
        srow[warp][lane] = a0;
        srow[warp][lane + 32] = a1;
        __syncwarp();

        if (lane == 0) {
            float* row = srow[warp];
            float m = row[0];
            #pragma unroll
            for (int e = 1; e < NE; e++) m = fmaxf(m, row[e]);
            float ssum = 0.f;
            #pragma unroll
            for (int e = 0; e < NE; e++) { float ex = __expf(row[e] - m); row[e] = ex; ssum += ex; }
            float inv = 1.0f / ssum;
            #pragma unroll
            for (int e = 0; e < NE; e++) row[e] *= inv;

            float* outw = out + (size_t)tok * TOPK;
            float* outi = out + (size_t)TOKENS * TOPK + (size_t)tok * TOPK;
            #pragma unroll
            for (int k = 0; k < TOPK; k++) {
                float best = -CUDART_INF_F; int bi = 0;
                #pragma unroll
                for (int e = 0; e < NE; e++) {
                    float b = row[e] + __ldg(&bias[e]);
                    if (b > best) { best = b; bi = e; }
                }
                outw[k] = row[bi];
                outi[k] = (float)bi;
                row[bi] = -CUDART_INF_F;
            }
        }
        __syncwarp();
    }
}

extern "C" void kernel_launch(void* const* d_in, const int* in_sizes, int n_in,
                              void* d_out, int out_size)
{
    const float* x    = (const float*)d_in[0];
    const float* w    = (const float*)d_in[1];
    const float* bias = (const float*)d_in[2];
    float* out = (float*)d_out;

    cudaFuncSetAttribute(gate_kernel, cudaFuncAttributeMaxDynamicSharedMemorySize, SMEM_BYTES);
    gate_kernel<<<TOKENS / BM, THREADS, SMEM_BYTES>>>(x, w, bias, out);
    fix_kernel<<<TOKENS / BM, 64>>>(x, w, bias, out);
}

// round 10
// speedup vs baseline: 1.7280x; 1.7280x over previous
#include <cuda_runtime.h>
#include <cstdint>
#include <math_constants.h>

#define TOKENS   32768
#define DIM      2048
#define NE       64
#define TOPK     6

#define BM       128              // tokens per CTA
#define BKT      32               // K per chunk
#define NCHUNK   (DIM / BKT)      // 64
#define THREADS  256              // 8 warps: 4 across M (32 rows), 2 across N (32 cols)

#define KB2      40               // bf16 row stride (elements): 32 + 8 pad -> conflict-free frags
#define ROWB     (KB2 * 2)        // 80 bytes per row

#define OFF_AH   0
#define OFF_AM   (BM * ROWB)
#define OFF_AL   (2 * BM * ROWB)
#define OFF_WH   (3 * BM * ROWB)
#define OFF_WM   (3 * BM * ROWB + NE * ROWB)
#define OFF_WL   (3 * BM * ROWB + 2 * NE * ROWB)
#define STAGE_B  (3 * BM * ROWB + 3 * NE * ROWB)   // 46080
#define BIAS_OFF (2 * STAGE_B)
#define SMEM_BYTES (BIAS_OFF + 256)

#define LSTR     66               // epilogue logits row stride (floats)
#define FLAG_GAP 2e-6f            // 20x above bf16-6-term logit noise (~1e-7)

// ---- flat flagged-token list ----
__device__ int g_nflag;
__device__ int g_flags[TOKENS];

__global__ void zero_kernel() { g_nflag = 0; }

// pack two fp32 -> bf16x2, round-to-nearest
__device__ __forceinline__ uint32_t pack_bf16(float hi, float lo) {
    uint32_t d;
    asm("cvt.rn.bf16x2.f32 %0, %1, %2;" : "=r"(d) : "f"(hi), "f"(lo));
    return d;
}
__device__ __forceinline__ float bf_lo(uint32_t p) { return __uint_as_float(p << 16); }
__device__ __forceinline__ float bf_hi(uint32_t p) { return __uint_as_float(p & 0xFFFF0000u); }

struct Tri { uint2 h, m, l; };
// 3-way bf16 split of 4 consecutive values (residual ~2^-25)
__device__ __forceinline__ Tri split4(float4 v) {
    Tri t;
    t.h.x = pack_bf16(v.y, v.x);
    t.h.y = pack_bf16(v.w, v.z);
    float r0 = v.x - bf_lo(t.h.x), r1 = v.y - bf_hi(t.h.x);
    float r2 = v.z - bf_lo(t.h.y), r3 = v.w - bf_hi(t.h.y);
    t.m.x = pack_bf16(r1, r0);
    t.m.y = pack_bf16(r3, r2);
    float s0 = r0 - bf_lo(t.m.x), s1 = r1 - bf_hi(t.m.x);
    float s2 = r2 - bf_lo(t.m.y), s3 = r3 - bf_hi(t.m.y);
    t.l.x = pack_bf16(s1, s0);
    t.l.y = pack_bf16(s3, s2);
    return t;
}

// m16n8k16 bf16 mma, f32 accumulate in-place
__device__ __forceinline__ void mma16(float* c, const uint32_t* a, uint32_t b0, uint32_t b1) {
    asm volatile(
        "mma.sync.aligned.m16n8k16.row.col.f32.bf16.bf16.f32 "
        "{%0,%1,%2,%3}, {%4,%5,%6,%7}, {%8,%9}, {%0,%1,%2,%3};"
        : "+f"(c[0]), "+f"(c[1]), "+f"(c[2]), "+f"(c[3])
        : "r"(a[0]), "r"(a[1]), "r"(a[2]), "r"(a[3]), "r"(b0), "r"(b1));
}

// ============================ PASS 1: bf16 6-term MMA GEMM + gate ============================
__global__ __launch_bounds__(THREADS, 2)
void gate_kernel(const float* __restrict__ x,
                 const float* __restrict__ w,
                 const float* __restrict__ bias,
                 float* __restrict__ out)
{
    extern __shared__ __align__(16) unsigned char smem[];
    float* sBias = reinterpret_cast<float*>(smem + BIAS_OFF);
    float* sLog  = reinterpret_cast<float*>(smem);   // epilogue overlay

    const int tid  = threadIdx.x;
    const int lane = tid & 31;
    const int wid  = tid >> 5;
    const int gid  = lane >> 2;
    const int tg   = lane & 3;
    const int m0   = (wid & 3) * 32;
    const int n0   = (wid >> 2) * 32;
    const int block_m = blockIdx.x * BM;

    if (tid < NE) sBias[tid] = bias[tid];

    const float* xg = x + (size_t)block_m * DIM;

    float acc[2][4][4];
    #pragma unroll
    for (int mt = 0; mt < 2; mt++)
        #pragma unroll
        for (int nt = 0; nt < 4; nt++)
            #pragma unroll
            for (int r = 0; r < 4; r++) acc[mt][nt][r] = 0.f;

    float4 xr[4], wr[2];
    int xtok[4], xcq[4], wexp[2], wcq[2];
    #pragma unroll
    for (int i = 0; i < 4; i++) {
        int li = i * THREADS + tid; xtok[i] = li >> 3; xcq[i] = li & 7;
    }
    #pragma unroll
    for (int i = 0; i < 2; i++) {
        int li = i * THREADS + tid; wexp[i] = li >> 3; wcq[i] = li & 7;
    }

    auto ldg_chunk = [&](int c) {
        int k0 = c * BKT;
        #pragma unroll
        for (int i = 0; i < 4; i++)
            xr[i] = *reinterpret_cast<const float4*>(xg + (size_t)xtok[i] * DIM + k0 + xcq[i] * 4);
        #pragma unroll
        for (int i = 0; i < 2; i++)
            wr[i] = *reinterpret_cast<const float4*>(w + (size_t)wexp[i] * DIM + k0 + wcq[i] * 4);
    };
    auto sts_chunk = [&](int s) {
        unsigned char* st = smem + s * STAGE_B;
        #pragma unroll
        for (int i = 0; i < 4; i++) {
            Tri t = split4(xr[i]);
            int off = xtok[i] * ROWB + xcq[i] * 8;
            *reinterpret_cast<uint2*>(st + OFF_AH + off) = t.h;
            *reinterpret_cast<uint2*>(st + OFF_AM + off) = t.m;
            *reinterpret_cast<uint2*>(st + OFF_AL + off) = t.l;
        }
        #pragma unroll
        for (int i = 0; i < 2; i++) {
            Tri t = split4(wr[i]);
            int off = wexp[i] * ROWB + wcq[i] * 8;
            *reinterpret_cast<uint2*>(st + OFF_WH + off) = t.h;
            *reinterpret_cast<uint2*>(st + OFF_WM + off) = t.m;
            *reinterpret_cast<uint2*>(st + OFF_WL + off) = t.l;
        }
    };

    ldg_chunk(0);
    sts_chunk(0);
    __syncthreads();
    ldg_chunk(1);

    for (int c = 0; c < NCHUNK; c++) {
        const int s = c & 1;
        if (c + 1 < NCHUNK) {
            sts_chunk(s ^ 1);
            if (c + 2 < NCHUNK) ldg_chunk(c + 2);
        }

        const unsigned char* st = smem + s * STAGE_B;
        const uint32_t* Ah = reinterpret_cast<const uint32_t*>(st + OFF_AH);
        const uint32_t* Am = reinterpret_cast<const uint32_t*>(st + OFF_AM);
        const uint32_t* Al = reinterpret_cast<const uint32_t*>(st + OFF_AL);
        const uint32_t* Wh = reinterpret_cast<const uint32_t*>(st + OFF_WH);
        const uint32_t* Wm = reinterpret_cast<const uint32_t*>(st + OFF_WM);
        const uint32_t* Wl = reinterpret_cast<const uint32_t*>(st + OFF_WL);

        #pragma unroll
        for (int q = 0; q < BKT / 16; q++) {
            const int kw = q * 8 + tg;

            uint32_t ah[2][4], am[2][4], al[2][4];
            #pragma unroll
            for (int mt = 0; mt < 2; mt++) {
                int r0 = (m0 + mt * 16 + gid) * (ROWB / 4);
                int r1 = r0 + 8 * (ROWB / 4);
                ah[mt][0] = Ah[r0 + kw];     ah[mt][1] = Ah[r1 + kw];
                ah[mt][2] = Ah[r0 + kw + 4]; ah[mt][3] = Ah[r1 + kw + 4];
                am[mt][0] = Am[r0 + kw];     am[mt][1] = Am[r1 + kw];
                am[mt][2] = Am[r0 + kw + 4]; am[mt][3] = Am[r1 + kw + 4];
                al[mt][0] = Al[r0 + kw];     al[mt][1] = Al[r1 + kw];
                al[mt][2] = Al[r0 + kw + 4]; al[mt][3] = Al[r1 + kw + 4];
            }

            #pragma unroll
            for (int nt = 0; nt < 4; nt++) {
                int rn = (n0 + nt * 8 + gid) * (ROWB / 4);
                uint32_t bh0 = Wh[rn + kw], bh1 = Wh[rn + kw + 4];
                uint32_t bm0 = Wm[rn + kw], bm1 = Wm[rn + kw + 4];
                uint32_t bl0 = Wl[rn + kw], bl1 = Wl[rn + kw + 4];
                #pragma unroll
                for (int mt = 0; mt < 2; mt++) {
                    float* cc = acc[mt][nt];
                    mma16(cc, ah[mt], bh0, bh1);
                    mma16(cc, ah[mt], bm0, bm1);
                    mma16(cc, am[mt], bh0, bh1);
                    mma16(cc, am[mt], bm0, bm1);
                    mma16(cc, ah[mt], bl0, bl1);
                    mma16(cc, al[mt], bh0, bh1);
                }
            }
        }
        __syncthreads();
    }

    // ---- dump logits ----
    #pragma unroll
    for (int mt = 0; mt < 2; mt++)
        #pragma unroll
        for (int nt = 0; nt < 4; nt++) {
            int row = m0 + mt * 16 + gid;
            int col = n0 + nt * 8 + tg * 2;
            *reinterpret_cast<float2*>(&sLog[row * LSTR + col]) =
                make_float2(acc[mt][nt][0], acc[mt][nt][1]);
            *reinterpret_cast<float2*>(&sLog[(row + 8) * LSTR + col]) =
                make_float2(acc[mt][nt][2], acc[mt][nt][3]);
        }
    __syncthreads();

    // ---- epilogue: softmax, top-6, ambiguity flag ----
    if (tid < BM) {
        float* row = sLog + tid * LSTR;

        float m = row[0];
        #pragma unroll
        for (int e = 1; e < NE; e++) m = fmaxf(m, row[e]);
        float ssum = 0.f;
        #pragma unroll
        for (int e = 0; e < NE; e++) { float ex = __expf(row[e] - m); row[e] = ex; ssum += ex; }
        float inv = 1.0f / ssum;
        #pragma unroll
        for (int e = 0; e < NE; e++) row[e] *= inv;

        const int t = block_m + tid;
        float* outw = out + (size_t)t * TOPK;
        float* outi = out + (size_t)TOKENS * TOPK + (size_t)t * TOPK;

        float prev = 0.f, minGap = CUDART_INF_F;
        #pragma unroll
        for (int k = 0; k < TOPK + 1; k++) {
            float best = -CUDART_INF_F; int bi = 0;
            #pragma unroll
            for (int e = 0; e < NE; e++) {
                float b = row[e] + sBias[e];
                if (b > best) { best = b; bi = e; }
            }
            if (k > 0) minGap = fminf(minGap, prev - best);
            prev = best;
            if (k < TOPK) {
                outw[k] = row[bi];
                outi[k] = (float)bi;
                row[bi] = -CUDART_INF_F;
            }
        }
        if (minGap < FLAG_GAP) {
            int idx = atomicAdd(&g_nflag, 1);
            g_flags[idx] = t;
        }
    }
}

// ============ PASS 2: fp32 recompute for flagged tokens, 1 block/token ============
// 128 threads: expert = tid&63, k-half = tid>>6 (two 1024-long k-ascending dots).
__global__ __launch_bounds__(128)
void fix_kernel(const float* __restrict__ x,
                const float* __restrict__ w,
                const float* __restrict__ bias,
                float* __restrict__ out)
{
    __shared__ float part[2][NE];
    __shared__ float row[NE];

    const int n = g_nflag;
    const int e    = threadIdx.x & 63;
    const int half = threadIdx.x >> 6;

    for (int i = blockIdx.x; i < n; i += gridDim.x) {
        const int tok = g_flags[i];
        const float* xt = x + (size_t)tok * DIM + half * (DIM / 2);
        const float* wt = w + (size_t)e * DIM + half * (DIM / 2);

        float a = 0.f;
        #pragma unroll 4
        for (int k = 0; k < DIM / 2; k += 4) {
            float4 xv = *reinterpret_cast<const float4*>(xt + k);
            float4 wv = *reinterpret_cast<const float4*>(wt + k);
            a = fmaf(xv.x, wv.x, a); a = fmaf(xv.y, wv.y, a);
            a = fmaf(xv.z, wv.z, a); a = fmaf(xv.w, wv.w, a);
        }
        part[half][e] = a;
        __syncthreads();

        if (threadIdx.x < NE) row[threadIdx.x] = part[0][threadIdx.x] + part[1][threadIdx.x];
        __syncthreads();

        if (threadIdx.x == 0) {
            float m = row[0];
            #pragma unroll
            for (int q = 1; q < NE; q++) m = fmaxf(m, row[q]);
            float ssum = 0.f;
            #pragma unroll
            for (int q = 0; q < NE; q++) { float ex = __expf(row[q] - m); row[q] = ex; ssum += ex; }
            float inv = 1.0f / ssum;
            #pragma unroll
            for (int q = 0; q < NE; q++) row[q] *= inv;

            float* outw = out + (size_t)tok * TOPK;
            float* outi = out + (size_t)TOKENS * TOPK + (size_t)tok * TOPK;
            #pragma unroll
            for (int k = 0; k < TOPK; k++) {
                float best = -CUDART_INF_F; int bi = 0;
                #pragma unroll
                for (int q = 0; q < NE; q++) {
                    float b = row[q] + __ldg(&bias[q]);
                    if (b > best) { best = b; bi = q; }
                }
                outw[k] = row[bi];
                outi[k] = (float)bi;
                row[bi] = -CUDART_INF_F;
            }
        }
        __syncthreads();
    }
}

extern "C" void kernel_launch(void* const* d_in, const int* in_sizes, int n_in,
                              void* d_out, int out_size)
{
    const float* x    = (const float*)d_in[0];
    const float* w    = (const float*)d_in[1];
    const float* bias = (const float*)d_in[2];
    float* out = (float*)d_out;

    cudaFuncSetAttribute(gate_kernel, cudaFuncAttributeMaxDynamicSharedMemorySize, SMEM_BYTES);
    zero_kernel<<<1, 1>>>();
    gate_kernel<<<TOKENS / BM, THREADS, SMEM_BYTES>>>(x, w, bias, out);
    fix_kernel<<<128, 128>>>(x, w, bias, out);
}

// round 11
// speedup vs baseline: 2.2960x; 1.3287x over previous
#include <cuda_runtime.h>
#include <cstdint>
#include <math_constants.h>

#define TOKENS   32768
#define DIM      2048
#define NE       64
#define TOPK     6

#define BM       128              // tokens per CTA
#define BKT      32               // K per chunk
#define NCHUNK   (DIM / BKT)      // 64
#define THREADS  256              // 8 warps: 4 across M (32 rows), 2 across N (32 cols)

#define KB2      40               // bf16 row stride (elements): 32 + 8 pad -> conflict-free frags
#define ROWB     (KB2 * 2)        // 80 bytes per row

#define OFF_AH   0
#define OFF_AM   (BM * ROWB)                       // 10240
#define OFF_WH   (2 * BM * ROWB)                   // 20480
#define OFF_WM   (2 * BM * ROWB + NE * ROWB)       // 25600
#define STAGE_B  (2 * BM * ROWB + 2 * NE * ROWB)   // 30720
#define BIAS_OFF (2 * STAGE_B)
#define SMEM_BYTES (BIAS_OFF + 256)

#define LSTR     66               // epilogue logits row stride (floats)
#define FLAG_GAP 4e-6f            // ~8x above 4-term bf16 score noise (~5e-7)

// ---- flat flagged-token list ----
__device__ int g_nflag;
__device__ int g_flags[TOKENS];

// pack two fp32 -> bf16x2, round-to-nearest
__device__ __forceinline__ uint32_t pack_bf16(float hi, float lo) {
    uint32_t d;
    asm("cvt.rn.bf16x2.f32 %0, %1, %2;" : "=r"(d) : "f"(hi), "f"(lo));
    return d;
}
__device__ __forceinline__ float bf_lo(uint32_t p) { return __uint_as_float(p << 16); }
__device__ __forceinline__ float bf_hi(uint32_t p) { return __uint_as_float(p & 0xFFFF0000u); }

struct Duo { uint2 h, m; };
// 2-way bf16 split of 4 consecutive values: v ~= h + m (residual ~2^-18 rel)
__device__ __forceinline__ Duo split4(float4 v) {
    Duo t;
    t.h.x = pack_bf16(v.y, v.x);
    t.h.y = pack_bf16(v.w, v.z);
    float r0 = v.x - bf_lo(t.h.x), r1 = v.y - bf_hi(t.h.x);
    float r2 = v.z - bf_lo(t.h.y), r3 = v.w - bf_hi(t.h.y);
    t.m.x = pack_bf16(r1, r0);
    t.m.y = pack_bf16(r3, r2);
    return t;
}

// m16n8k16 bf16 mma, f32 accumulate in-place
__device__ __forceinline__ void mma16(float* c, const uint32_t* a, uint32_t b0, uint32_t b1) {
    asm volatile(
        "mma.sync.aligned.m16n8k16.row.col.f32.bf16.bf16.f32 "
        "{%0,%1,%2,%3}, {%4,%5,%6,%7}, {%8,%9}, {%0,%1,%2,%3};"
        : "+f"(c[0]), "+f"(c[1]), "+f"(c[2]), "+f"(c[3])
        : "r"(a[0]), "r"(a[1]), "r"(a[2]), "r"(a[3]), "r"(b0), "r"(b1));
}

// ============================ PASS 1: bf16 4-term MMA GEMM + gate ============================
__global__ __launch_bounds__(THREADS, 2)
void gate_kernel(const float* __restrict__ x,
                 const float* __restrict__ w,
                 const float* __restrict__ bias,
                 float* __restrict__ out)
{
    extern __shared__ __align__(16) unsigned char smem[];
    float* sBias = reinterpret_cast<float*>(smem + BIAS_OFF);
    float* sLog  = reinterpret_cast<float*>(smem);   // epilogue overlay

    const int tid  = threadIdx.x;
    const int lane = tid & 31;
    const int wid  = tid >> 5;
    const int gid  = lane >> 2;
    const int tg   = lane & 3;
    const int m0   = (wid & 3) * 32;
    const int n0   = (wid >> 2) * 32;
    const int block_m = blockIdx.x * BM;

    if (tid < NE) sBias[tid] = bias[tid];

    const float* xg = x + (size_t)block_m * DIM;

    float acc[2][4][4];
    #pragma unroll
    for (int mt = 0; mt < 2; mt++)
        #pragma unroll
        for (int nt = 0; nt < 4; nt++)
            #pragma unroll
            for (int r = 0; r < 4; r++) acc[mt][nt][r] = 0.f;

    float4 xr[4], wr[2];
    int xtok[4], xcq[4], wexp[2], wcq[2];
    #pragma unroll
    for (int i = 0; i < 4; i++) {
        int li = i * THREADS + tid; xtok[i] = li >> 3; xcq[i] = li & 7;
    }
    #pragma unroll
    for (int i = 0; i < 2; i++) {
        int li = i * THREADS + tid; wexp[i] = li >> 3; wcq[i] = li & 7;
    }

    auto ldg_chunk = [&](int c) {
        int k0 = c * BKT;
        #pragma unroll
        for (int i = 0; i < 4; i++)
            xr[i] = *reinterpret_cast<const float4*>(xg + (size_t)xtok[i] * DIM + k0 + xcq[i] * 4);
        #pragma unroll
        for (int i = 0; i < 2; i++)
            wr[i] = *reinterpret_cast<const float4*>(w + (size_t)wexp[i] * DIM + k0 + wcq[i] * 4);
    };
    auto sts_chunk = [&](int s) {
        unsigned char* st = smem + s * STAGE_B;
        #pragma unroll
        for (int i = 0; i < 4; i++) {
            Duo t = split4(xr[i]);
            int off = xtok[i] * ROWB + xcq[i] * 8;
            *reinterpret_cast<uint2*>(st + OFF_AH + off) = t.h;
            *reinterpret_cast<uint2*>(st + OFF_AM + off) = t.m;
        }
        #pragma unroll
        for (int i = 0; i < 2; i++) {
            Duo t = split4(wr[i]);
            int off = wexp[i] * ROWB + wcq[i] * 8;
            *reinterpret_cast<uint2*>(st + OFF_WH + off) = t.h;
            *reinterpret_cast<uint2*>(st + OFF_WM + off) = t.m;
        }
    };

    ldg_chunk(0);
    sts_chunk(0);
    __syncthreads();
    ldg_chunk(1);

    for (int c = 0; c < NCHUNK; c++) {
        const int s = c & 1;
        if (c + 1 < NCHUNK) {
            sts_chunk(s ^ 1);
            if (c + 2 < NCHUNK) ldg_chunk(c + 2);
        }

        const unsigned char* st = smem + s * STAGE_B;
        const uint32_t* Ah = reinterpret_cast<const uint32_t*>(st + OFF_AH);
        const uint32_t* Am = reinterpret_cast<const uint32_t*>(st + OFF_AM);
        const uint32_t* Wh = reinterpret_cast<const uint32_t*>(st + OFF_WH);
        const uint32_t* Wm = reinterpret_cast<const uint32_t*>(st + OFF_WM);

        #pragma unroll
        for (int q = 0; q < BKT / 16; q++) {
            const int kw = q * 8 + tg;

            uint32_t ah[2][4], am[2][4];
            #pragma unroll
            for (int mt = 0; mt < 2; mt++) {
                int r0 = (m0 + mt * 16 + gid) * (ROWB / 4);
                int r1 = r0 + 8 * (ROWB / 4);
                ah[mt][0] = Ah[r0 + kw];     ah[mt][1] = Ah[r1 + kw];
                ah[mt][2] = Ah[r0 + kw + 4]; ah[mt][3] = Ah[r1 + kw + 4];
                am[mt][0] = Am[r0 + kw];     am[mt][1] = Am[r1 + kw];
                am[mt][2] = Am[r0 + kw + 4]; am[mt][3] = Am[r1 + kw + 4];
            }

            #pragma unroll
            for (int nt = 0; nt < 4; nt++) {
                int rn = (n0 + nt * 8 + gid) * (ROWB / 4);
                uint32_t bh0 = Wh[rn + kw], bh1 = Wh[rn + kw + 4];
                uint32_t bm0 = Wm[rn + kw], bm1 = Wm[rn + kw + 4];
                #pragma unroll
                for (int mt = 0; mt < 2; mt++) {
                    float* cc = acc[mt][nt];
                    mma16(cc, ah[mt], bh0, bh1);   // hi*hi
                    mma16(cc, ah[mt], bm0, bm1);   // hi*mid
                    mma16(cc, am[mt], bh0, bh1);   // mid*hi
                    mma16(cc, am[mt], bm0, bm1);   // mid*mid
                }
            }
        }
        __syncthreads();
    }

    // ---- dump logits ----
    #pragma unroll
    for (int mt = 0; mt < 2; mt++)
        #pragma unroll
        for (int nt = 0; nt < 4; nt++) {
            int row = m0 + mt * 16 + gid;
            int col = n0 + nt * 8 + tg * 2;
            *reinterpret_cast<float2*>(&sLog[row * LSTR + col]) =
                make_float2(acc[mt][nt][0], acc[mt][nt][1]);
            *reinterpret_cast<float2*>(&sLog[(row + 8) * LSTR + col]) =
                make_float2(acc[mt][nt][2], acc[mt][nt][3]);
        }
    __syncthreads();

    // ---- epilogue: softmax, top-6, ambiguity flag ----
    if (tid < BM) {
        float* row = sLog + tid * LSTR;

        float m = row[0];
        #pragma unroll
        for (int e = 1; e < NE; e++) m = fmaxf(m, row[e]);
        float ssum = 0.f;
        #pragma unroll
        for (int e = 0; e < NE; e++) { float ex = __expf(row[e] - m); row[e] = ex; ssum += ex; }
        float inv = 1.0f / ssum;
        #pragma unroll
        for (int e = 0; e < NE; e++) row[e] *= inv;

        const int t = block_m + tid;
        float* outw = out + (size_t)t * TOPK;
        float* outi = out + (size_t)TOKENS * TOPK + (size_t)t * TOPK;

        float prev = 0.f, minGap = CUDART_INF_F;
        #pragma unroll
        for (int k = 0; k < TOPK + 1; k++) {
            float best = -CUDART_INF_F; int bi = 0;
            #pragma unroll
            for (int e = 0; e < NE; e++) {
                float b = row[e] + sBias[e];
                if (b > best) { best = b; bi = e; }
            }
            if (k > 0) minGap = fminf(minGap, prev - best);
            prev = best;
            if (k < TOPK) {
                outw[k] = row[bi];
                outi[k] = (float)bi;
                row[bi] = -CUDART_INF_F;
            }
        }
        if (minGap < FLAG_GAP) {
            int idx = atomicAdd(&g_nflag, 1);
            g_flags[idx] = t;
        }
    }
}

// ============ PASS 2: fp32 recompute for flagged tokens, 1 block/token ============
__global__ __launch_bounds__(128)
void fix_kernel(const float* __restrict__ x,
                const float* __restrict__ w,
                const float* __restrict__ bias,
                float* __restrict__ out)
{
    __shared__ float part[2][NE];
    __shared__ float row[NE];

    const int n = g_nflag;
    const int e    = threadIdx.x & 63;
    const int half = threadIdx.x >> 6;

    for (int i = blockIdx.x; i < n; i += gridDim.x) {
        const int tok = g_flags[i];
        const float* xt = x + (size_t)tok * DIM + half * (DIM / 2);
        const float* wt = w + (size_t)e * DIM + half * (DIM / 2);

        float a = 0.f;
        #pragma unroll 4
        for (int k = 0; k < DIM / 2; k += 4) {
            float4 xv = *reinterpret_cast<const float4*>(xt + k);
            float4 wv = *reinterpret_cast<const float4*>(wt + k);
            a = fmaf(xv.x, wv.x, a); a = fmaf(xv.y, wv.y, a);
            a = fmaf(xv.z, wv.z, a); a = fmaf(xv.w, wv.w, a);
        }
        part[half][e] = a;
        __syncthreads();

        if (threadIdx.x < NE) row[threadIdx.x] = part[0][threadIdx.x] + part[1][threadIdx.x];
        __syncthreads();

        if (threadIdx.x == 0) {
            float m = row[0];
            #pragma unroll
            for (int q = 1; q < NE; q++) m = fmaxf(m, row[q]);
            float ssum = 0.f;
            #pragma unroll
            for (int q = 0; q < NE; q++) { float ex = __expf(row[q] - m); row[q] = ex; ssum += ex; }
            float inv = 1.0f / ssum;
            #pragma unroll
            for (int q = 0; q < NE; q++) row[q] *= inv;

            float* outw = out + (size_t)tok * TOPK;
            float* outi = out + (size_t)TOKENS * TOPK + (size_t)tok * TOPK;
            #pragma unroll
            for (int k = 0; k < TOPK; k++) {
                float best = -CUDART_INF_F; int bi = 0;
                #pragma unroll
                for (int q = 0; q < NE; q++) {
                    float b = row[q] + __ldg(&bias[q]);
                    if (b > best) { best = b; bi = q; }
                }
                outw[k] = row[bi];
                outi[k] = (float)bi;
                row[bi] = -CUDART_INF_F;
            }
        }
        __syncthreads();
    }
}

extern "C" void kernel_launch(void* const* d_in, const int* in_sizes, int n_in,
                              void* d_out, int out_size)
{
    const float* x    = (const float*)d_in[0];
    const float* w    = (const float*)d_in[1];
    const float* bias = (const float*)d_in[2];
    float* out = (float*)d_out;

    void* nflag_ptr = nullptr;
    cudaGetSymbolAddress(&nflag_ptr, g_nflag);
    cudaMemsetAsync(nflag_ptr, 0, sizeof(int));

    cudaFuncSetAttribute(gate_kernel, cudaFuncAttributeMaxDynamicSharedMemorySize, SMEM_BYTES);
    gate_kernel<<<TOKENS / BM, THREADS, SMEM_BYTES>>>(x, w, bias, out);
    fix_kernel<<<256, 128>>>(x, w, bias, out);
}